// round 1
// baseline (speedup 1.0000x reference)
#include <cuda_runtime.h>

// Problem shape (fixed by the dataset)
constexpr int Bsz = 256;
constexpr int Lsz = 65536;
constexpr int Tc  = 128;            // chunk length (timesteps per thread)
constexpr int Cc  = Lsz / Tc;       // 512 chunks per row

// Paul Kellet pink filter coefficients
constexpr float A0 = 0.99886f, A1 = 0.99332f, A2 = 0.969f,
                A3 = 0.8665f,  A4 = 0.55f,    A5 = -0.7616f;
constexpr float C0 = 0.0555179f, C1 = 0.0750759f, C2 = 0.153852f,
                C3 = 0.3104856f, C4 = 0.5329522f, C5 = -0.016898f;
constexpr float DIRECT = 0.5362f, OUT_GAIN = 0.11f, B6_GAIN = 0.115926f;

// a^T computed exactly at compile time (double accumulation)
constexpr float cpow(double a, int n) {
    double r = 1.0;
    for (int i = 0; i < n; ++i) r *= a;
    return (float)r;
}
constexpr float AT0 = cpow((double)A0, Tc);
constexpr float AT1 = cpow((double)A1, Tc);
constexpr float AT2 = cpow((double)A2, Tc);
constexpr float AT3 = cpow((double)A3, Tc);
constexpr float AT4 = cpow((double)A4, Tc);
constexpr float AT5 = cpow((double)A5, Tc);

// Scratch: per-chunk 6 pole states.
// pass1 writes local-final states; pass2 overwrites in-place with
// exclusive-scan init states; pass3 reads init states.
// Layout [k][b][6] so pass2 (one thread per row b) reads/writes coalesced-ish.
__device__ float g_st[(size_t)Cc * Bsz * 6];

// ---------------------------------------------------------------------------
// Pass 1: per-chunk local pole states with zero initial condition.
// ---------------------------------------------------------------------------
__global__ void __launch_bounds__(256) k_pass1(const float* __restrict__ white) {
    int tid = blockIdx.x * 256 + threadIdx.x;
    int b = tid / Cc;
    int k = tid % Cc;

    const float4* w4 = reinterpret_cast<const float4*>(
        white + (size_t)b * Lsz + (size_t)k * Tc);

    float s0 = 0.f, s1 = 0.f, s2 = 0.f, s3 = 0.f, s4 = 0.f, s5 = 0.f;

#pragma unroll 4
    for (int t = 0; t < Tc / 4; ++t) {
        float4 w = w4[t];
#define P1STEP(x)                                \
        {                                        \
            s0 = fmaf(A0, s0, C0 * (x));         \
            s1 = fmaf(A1, s1, C1 * (x));         \
            s2 = fmaf(A2, s2, C2 * (x));         \
            s3 = fmaf(A3, s3, C3 * (x));         \
            s4 = fmaf(A4, s4, C4 * (x));         \
            s5 = fmaf(A5, s5, C5 * (x));         \
        }
        P1STEP(w.x) P1STEP(w.y) P1STEP(w.z) P1STEP(w.w)
#undef P1STEP
    }

    float* o = g_st + ((size_t)k * Bsz + b) * 6;
    o[0] = s0; o[1] = s1; o[2] = s2; o[3] = s3; o[4] = s4; o[5] = s5;
}

// ---------------------------------------------------------------------------
// Pass 2: exclusive scan across chunks, one thread per row, in place.
//   init(k) = A^T * init(k-1) + local(k-1),  init(0) = 0
// ---------------------------------------------------------------------------
__global__ void k_pass2() {
    int b = threadIdx.x;                       // 256 threads, 1 block
    float r0 = 0.f, r1 = 0.f, r2 = 0.f, r3 = 0.f, r4 = 0.f, r5 = 0.f;

    for (int k = 0; k < Cc; ++k) {
        float* p = g_st + ((size_t)k * Bsz + b) * 6;
        float t0 = p[0], t1 = p[1], t2 = p[2], t3 = p[3], t4 = p[4], t5 = p[5];
        p[0] = r0; p[1] = r1; p[2] = r2; p[3] = r3; p[4] = r4; p[5] = r5;
        r0 = fmaf(AT0, r0, t0);
        r1 = fmaf(AT1, r1, t1);
        r2 = fmaf(AT2, r2, t2);
        r3 = fmaf(AT3, r3, t3);
        r4 = fmaf(AT4, r4, t4);
        r5 = fmaf(AT5, r5, t5);
    }
}

// ---------------------------------------------------------------------------
// Pass 3: re-run each chunk from the correct initial state, emit pink.
// b6 state is a pure one-sample delay: init from white[chunk_start-1].
// ---------------------------------------------------------------------------
__global__ void __launch_bounds__(256) k_pass3(const float* __restrict__ white,
                                               float* __restrict__ pink) {
    int tid = blockIdx.x * 256 + threadIdx.x;
    int b = tid / Cc;
    int k = tid % Cc;

    const float* base = white + (size_t)b * Lsz + (size_t)k * Tc;
    const float4* w4 = reinterpret_cast<const float4*>(base);
    float4* p4 = reinterpret_cast<float4*>(pink + (size_t)b * Lsz + (size_t)k * Tc);

    const float* st = g_st + ((size_t)k * Bsz + b) * 6;
    float s0 = st[0], s1 = st[1], s2 = st[2], s3 = st[3], s4 = st[4], s5 = st[5];
    float b6 = (k > 0) ? (B6_GAIN * base[-1]) : 0.f;

#pragma unroll 2
    for (int t = 0; t < Tc / 4; ++t) {
        float4 w = w4[t];
        float4 o;
#define P3STEP(x, y)                                                       \
        {                                                                  \
            s0 = fmaf(A0, s0, C0 * (x));                                   \
            s1 = fmaf(A1, s1, C1 * (x));                                   \
            s2 = fmaf(A2, s2, C2 * (x));                                   \
            s3 = fmaf(A3, s3, C3 * (x));                                   \
            s4 = fmaf(A4, s4, C4 * (x));                                   \
            s5 = fmaf(A5, s5, C5 * (x));                                   \
            float sum = ((s0 + s1) + (s2 + s3)) + (s4 + s5);               \
            (y) = fmaf(DIRECT, (x), sum + b6) * OUT_GAIN;                  \
            b6 = B6_GAIN * (x);                                            \
        }
        P3STEP(w.x, o.x)
        P3STEP(w.y, o.y)
        P3STEP(w.z, o.z)
        P3STEP(w.w, o.w)
#undef P3STEP
        p4[t] = o;
    }
}

// ---------------------------------------------------------------------------
extern "C" void kernel_launch(void* const* d_in, const int* in_sizes, int n_in,
                              void* d_out, int out_size) {
    const float* white = (const float*)d_in[0];
    float* pink = (float*)d_out;
    (void)in_sizes; (void)n_in; (void)out_size;

    k_pass1<<<(Bsz * Cc) / 256, 256>>>(white);
    k_pass2<<<1, 256>>>();
    k_pass3<<<(Bsz * Cc) / 256, 256>>>(white, pink);
}

// round 5
// speedup vs baseline: 3.9915x; 3.9915x over previous
#include <cuda_runtime.h>

// Problem shape (fixed by the dataset)
constexpr int Bsz = 256;
constexpr int Lsz = 65536;
constexpr int Tc  = 128;          // samples per chunk (per thread)
constexpr int Cc  = Lsz / Tc;     // 512 chunks per row = threads per block
constexpr int NW  = Cc / 32;      // 16 warps per block

// Paul Kellet pink filter coefficients (scalar constexprs fold fine in device code)
constexpr float A0 = 0.99886f, A1 = 0.99332f, A2 = 0.969f,
                A3 = 0.8665f,  A4 = 0.55f,    A5 = -0.7616f;
constexpr float DIRECT = 0.5362f, OUT_GAIN = 0.11f, B6_GAIN = 0.115926f;
constexpr float OGD = OUT_GAIN * DIRECT;     // coeff on current white
constexpr float OGB = OUT_GAIN * B6_GAIN;    // coeff on previous white

// Flush-to-zero guard: nvcc's constexpr evaluator hard-errors on FP underflow,
// so clamp tiny intermediates to exact 0 (mathematically 0 at fp32 precision).
constexpr double ftz(double x) {
    return (x < 1e-100 && x > -1e-100) ? 0.0 : x;
}
// compile-time pow (double accumulation, binary exponentiation, FTZ-guarded)
constexpr double cdpow(double a, long long n) {
    double r = 1.0, p = a;
    while (n > 0) {
        if (n & 1) r = ftz(r * p);
        p = ftz(p * p);
        n >>= 1;
    }
    return r;
}
constexpr float cpowf(double a, long long n) {
    double r = cdpow(a, n);
    if (r < 1e-37 && r > -1e-37) return 0.0f;
    return (float)r;
}

// Coefficient tables must live in device memory space: plain constexpr arrays
// are host-only symbols without --expt-relaxed-constexpr.
__device__ __constant__ float A_[6] = {A0, A1, A2, A3, A4, A5};
__device__ __constant__ float C_[6] = {0.0555179f, 0.0750759f, 0.153852f,
                                       0.3104856f, 0.5329522f, -0.016898f};

// warp-scan weights  W_[p][j] = A_p^(Tc * 2^j),        j = 0..4 (d=1..16)
// cross-warp weights X_[p][j] = A_p^(Tc * 32 * 2^j),   j = 0..3 (d=1..8)
// per-chunk multiplier M_[p]  = A_p^Tc (float, for per-lane pow)
#define WARR(A) { cpowf(A,(long long)Tc), cpowf(A,(long long)Tc*2), cpowf(A,(long long)Tc*4), \
                  cpowf(A,(long long)Tc*8), cpowf(A,(long long)Tc*16) }
#define XARR(A) { cpowf(A,(long long)Tc*32), cpowf(A,(long long)Tc*64), \
                  cpowf(A,(long long)Tc*128), cpowf(A,(long long)Tc*256) }
__device__ __constant__ float W_[6][5] =
    { WARR(A0), WARR(A1), WARR(A2), WARR(A3), WARR(A4), WARR(A5) };
__device__ __constant__ float X_[6][4] =
    { XARR(A0), XARR(A1), XARR(A2), XARR(A3), XARR(A4), XARR(A5) };
__device__ __constant__ float M_[6] =
    { cpowf(A0,Tc), cpowf(A1,Tc), cpowf(A2,Tc),
      cpowf(A3,Tc), cpowf(A4,Tc), cpowf(A5,Tc) };

// float binary pow, n in [1, 32] (6 bits, fully unrolled — no FP64 on the hot path)
__device__ __forceinline__ float fpow6(float m, int n) {
    float r = 1.f, p = m;
#pragma unroll
    for (int i = 0; i < 6; ++i) { if (n & 1) r *= p; p *= p; n >>= 1; }
    return r;
}

// ---------------------------------------------------------------------------
// One block per row. Three phases in one kernel:
//   1) per-chunk local pole states (zero init)
//   2) Kogge-Stone scan over chunks -> exact init state per chunk
//   3) re-run chunk from init state, emit pink
// ---------------------------------------------------------------------------
__global__ void __launch_bounds__(Cc) k_pink(const float* __restrict__ white,
                                             float* __restrict__ pink) {
    const int b = blockIdx.x;
    const int k = threadIdx.x;              // chunk index within row
    const int lane = k & 31, wid = k >> 5;

    const size_t off = (size_t)b * Lsz + (size_t)k * Tc;
    const float4* w4 = reinterpret_cast<const float4*>(white + off);

    // ---- Phase 1: local pole states with zero initial condition
    float s[6];
#pragma unroll
    for (int p = 0; p < 6; ++p) s[p] = 0.f;

#pragma unroll 4
    for (int t = 0; t < Tc / 4; ++t) {
        float4 w = w4[t];
        float xs[4] = {w.x, w.y, w.z, w.w};
#pragma unroll
        for (int i = 0; i < 4; ++i)
#pragma unroll
            for (int p = 0; p < 6; ++p)
                s[p] = fmaf(A_[p], s[p], C_[p] * xs[i]);
    }

    // ---- Phase 2: inclusive scan I(k) = sum_{j<=k} M^(k-j) local(j)
    float v[6];
#pragma unroll
    for (int p = 0; p < 6; ++p) v[p] = s[p];

    // warp-level Kogge-Stone (d = 1,2,4,8,16)
#pragma unroll
    for (int j = 0; j < 5; ++j) {
        const int d = 1 << j;
        float u[6];
#pragma unroll
        for (int p = 0; p < 6; ++p) u[p] = __shfl_up_sync(0xffffffffu, v[p], d);
        if (lane >= d)
#pragma unroll
            for (int p = 0; p < 6; ++p) v[p] = fmaf(W_[p][j], u[p], v[p]);
    }

    __shared__ float tot[NW][6];
    __shared__ float pre[NW][6];
    if (lane == 31)
#pragma unroll
        for (int p = 0; p < 6; ++p) tot[wid][p] = v[p];
    __syncthreads();

    // warp 0 scans the 16 warp totals with weight X = M^32 (d = 1,2,4,8)
    if (wid == 0) {
        float t[6];
#pragma unroll
        for (int p = 0; p < 6; ++p) t[p] = (lane < NW) ? tot[lane][p] : 0.f;
#pragma unroll
        for (int j = 0; j < 4; ++j) {
            const int d = 1 << j;
            float u[6];
#pragma unroll
            for (int p = 0; p < 6; ++p) u[p] = __shfl_up_sync(0xffffffffu, t[p], d);
            if (lane >= d)
#pragma unroll
                for (int p = 0; p < 6; ++p) t[p] = fmaf(X_[p][j], u[p], t[p]);
        }
        // exclusive prefix E_w = inclusive(w-1), E_0 = 0
#pragma unroll
        for (int p = 0; p < 6; ++p) {
            float e = __shfl_up_sync(0xffffffffu, t[p], 1);
            if (lane == 0) e = 0.f;
            if (lane < NW) pre[lane][p] = e;
        }
    }
    __syncthreads();

    // combine: I(k) = v + M^(lane+1) * E_w
    float pw[6], lf[6];
#pragma unroll
    for (int p = 0; p < 6; ++p) pw[p] = pre[wid][p];
#pragma unroll
    for (int p = 0; p < 6; ++p) lf[p] = fpow6(M_[p], lane + 1);
#pragma unroll
    for (int p = 0; p < 6; ++p) v[p] = fmaf(lf[p], pw[p], v[p]);

    // init state for this chunk = I(k-1); lane 0 takes E_w (k=0 -> E_0 = 0)
    float ini[6];
#pragma unroll
    for (int p = 0; p < 6; ++p) {
        float u = __shfl_up_sync(0xffffffffu, v[p], 1);
        ini[p] = (lane == 0) ? pw[p] : u;
    }

    // ---- Phase 3: re-run chunk from exact init, emit pink
    float xprev = (k > 0) ? white[off - 1] : 0.f;
#pragma unroll
    for (int p = 0; p < 6; ++p) s[p] = ini[p];
    float4* o4 = reinterpret_cast<float4*>(pink + off);

#pragma unroll 2
    for (int t = 0; t < Tc / 4; ++t) {
        float4 w = w4[t];
        float xs[4] = {w.x, w.y, w.z, w.w};
        float ys[4];
#pragma unroll
        for (int i = 0; i < 4; ++i) {
#pragma unroll
            for (int p = 0; p < 6; ++p)
                s[p] = fmaf(A_[p], s[p], C_[p] * xs[i]);
            float sum = ((s[0] + s[1]) + (s[2] + s[3])) + (s[4] + s[5]);
            ys[i] = fmaf(OUT_GAIN, sum, fmaf(OGD, xs[i], OGB * xprev));
            xprev = xs[i];
        }
        float4 o;
        o.x = ys[0]; o.y = ys[1]; o.z = ys[2]; o.w = ys[3];
        o4[t] = o;
    }
}

// ---------------------------------------------------------------------------
extern "C" void kernel_launch(void* const* d_in, const int* in_sizes, int n_in,
                              void* d_out, int out_size) {
    const float* white = (const float*)d_in[0];
    float* pink = (float*)d_out;
    (void)in_sizes; (void)n_in; (void)out_size;

    k_pink<<<Bsz, Cc>>>(white, pink);
}